// round 14
// baseline (speedup 1.0000x reference)
#include <cuda_runtime.h>

#define V_MAX 100000

// -------- scratch (static device arrays; no allocation) --------
__device__ float g_f1[V_MAX * 32];
__device__ float g_h2[V_MAX * 32];
__device__ float g_f2p[4][V_MAX * 64];   // k4 partial sums (channel quarters)

// -------- f32x2 packed helpers --------
__device__ __forceinline__ unsigned long long pack2(float lo, float hi) {
    unsigned long long r;
    asm("mov.b64 %0, {%1, %2};" : "=l"(r) : "f"(lo), "f"(hi));
    return r;
}
__device__ __forceinline__ void unpack2(unsigned long long v, float& lo, float& hi) {
    asm("mov.b64 {%0, %1}, %2;" : "=f"(lo), "=f"(hi) : "l"(v));
}
__device__ __forceinline__ unsigned long long fma2(unsigned long long a,
                                                   unsigned long long b,
                                                   unsigned long long c) {
    unsigned long long d;
    asm("fma.rn.f32x2 %0, %1, %2, %3;" : "=l"(d) : "l"(a), "l"(b), "l"(c));
    return d;
}
__device__ __forceinline__ unsigned long long add2(unsigned long long a,
                                                   unsigned long long b) {
    unsigned long long d;
    asm("add.rn.f32x2 %0, %1, %2;" : "=l"(d) : "l"(a), "l"(b));
    return d;
}

// ============================================================
// K12 (fused K1+K2): block covers 8 vertices + 2 halo.
// ============================================================
#define K12_VPB 8
__global__ __launch_bounds__(320) void k12(const float* __restrict__ vp,
                                           const int* __restrict__ nb1,
                                           const float* __restrict__ wv1,
                                           const float* __restrict__ bv1,
                                           const float* __restrict__ w1,
                                           const float* __restrict__ b1, int V) {
    __shared__ float sh[K12_VPB + 2];
    int tid = threadIdx.x, w = tid >> 5, lane = tid & 31;
    int vbase = blockIdx.x * K12_VPB;
    int vg = vbase - 1 + w;                      // w in 0..9

    float hval = 0.f;
    if ((unsigned)vg < (unsigned)V) {
        int j = nb1[(size_t)vg * 32 + lane];
        if ((unsigned)j >= (unsigned)V) j = 0;   // defensive clamp
        float g = vp[j];
        float c0 = __ldg(wv1 + 0), c1 = __ldg(wv1 + 1), c2 = __ldg(wv1 + 2);
        float b  = __ldg(bv1);
        float gm = __shfl_up_sync(0xffffffffu, g, 1);
        if (lane == 0) gm = 0.f;
        float gp = __shfl_down_sync(0xffffffffu, g, 1);
        if (lane == 31) gp = 0.f;
        float a = fmaxf(c0 * gm + c1 * g + c2 * gp + b, 0.f);
        #pragma unroll
        for (int s = 16; s > 0; s >>= 1) a += __shfl_xor_sync(0xffffffffu, a, s);
        hval = a * (1.0f / 32.0f);
    }
    if (lane == 0) sh[w] = hval;                 // out-of-range vg -> 0 (pad)
    __syncthreads();

    if (tid < 256) {
        int lv = tid >> 5;
        int v = vbase + lv;
        if (v < V) {
            float hm = sh[lv], hc = sh[lv + 1], hp = sh[lv + 2];
            int c = lane;
            g_f1[(size_t)v * 32 + c] =
                hm * __ldg(w1 + c * 3 + 0) + hc * __ldg(w1 + c * 3 + 1)
              + hp * __ldg(w1 + c * 3 + 2) + __ldg(b1 + c);
        }
    }
}

// ============================================================
// K3: h2[v,c] = mean_n relu(conv_k3_over_n( f1[nb2[v,n], c] ))
//     warp per vertex, lane = channel c; 32 row loads upfront (MLP=32).
// ============================================================
__global__ void k3_h2(const int* __restrict__ nb2, const float* __restrict__ wv2,
                      const float* __restrict__ bv2, int V) {
    int warp = (blockIdx.x * blockDim.x + threadIdx.x) >> 5;
    int lane = threadIdx.x & 31;
    if (warp >= V) return;
    int idx = nb2[(size_t)warp * 32 + lane];
    if ((unsigned)idx >= (unsigned)V) idx = 0;  // defensive clamp

    float gv[32];
    #pragma unroll
    for (int p = 0; p < 32; p++) {
        int rn = __shfl_sync(0xffffffffu, idx, p);
        gv[p] = __ldg(&g_f1[(size_t)rn * 32 + lane]);  // coalesced 128B row
    }
    float w0 = __ldg(wv2 + 0), w1 = __ldg(wv2 + 1), w2 = __ldg(wv2 + 2);
    float b  = __ldg(bv2);
    float acc = 0.f;
    #pragma unroll
    for (int p = 0; p < 32; p++) {
        float gm = (p > 0)  ? gv[p - 1] : 0.f;
        float gp = (p < 31) ? gv[p + 1] : 0.f;
        acc += fmaxf(w0 * gm + w1 * gv[p] + w2 * gp + b, 0.f);
    }
    g_h2[(size_t)warp * 32 + lane] = acc * (1.0f / 32.0f);
}

// ============================================================
// K4: 4-way channel split, rolling tap-dots, ull2 row loads.
// ============================================================
#define K4_STRIP 64

__device__ __forceinline__ void k4q_dots(
    int r, int V, int q,
    const unsigned long long* wp0, const unsigned long long* wp1,
    const unsigned long long* wp2,
    float& e0, float& e1, float& e2)
{
    if ((unsigned)r >= (unsigned)V) { e0 = 0.f; e1 = 0.f; e2 = 0.f; return; }
    const ulonglong2* row = (const ulonglong2*)(g_h2 + (size_t)r * 32 + q * 8);
    ulonglong2 ua = __ldg(row);
    ulonglong2 ub = __ldg(row + 1);
    unsigned long long a0 = fma2(ua.x, wp0[0], 0ull);
    unsigned long long a1 = fma2(ua.x, wp1[0], 0ull);
    unsigned long long a2 = fma2(ua.x, wp2[0], 0ull);
    a0 = fma2(ua.y, wp0[1], a0);  a1 = fma2(ua.y, wp1[1], a1);  a2 = fma2(ua.y, wp2[1], a2);
    a0 = fma2(ub.x, wp0[2], a0);  a1 = fma2(ub.x, wp1[2], a1);  a2 = fma2(ub.x, wp2[2], a2);
    a0 = fma2(ub.y, wp0[3], a0);  a1 = fma2(ub.y, wp1[3], a1);  a2 = fma2(ub.y, wp2[3], a2);
    float lo, hi;
    unpack2(a0, lo, hi); e0 = lo + hi;
    unpack2(a1, lo, hi); e1 = lo + hi;
    unpack2(a2, lo, hi); e2 = lo + hi;
}

__global__ __launch_bounds__(256, 4) void k4_f2(const float* __restrict__ w2,
                                                const float* __restrict__ b2, int V) {
    int tid = threadIdx.x;
    int o = tid & 63;
    int q = tid >> 6;                            // channel quarter 0..3

    const float* wo = w2 + o * 96 + q * 24;
    unsigned long long wp0[4], wp1[4], wp2[4];
    #pragma unroll
    for (int j = 0; j < 4; j++) {
        wp0[j] = pack2(__ldg(wo + 6 * j + 0), __ldg(wo + 6 * j + 3));
        wp1[j] = pack2(__ldg(wo + 6 * j + 1), __ldg(wo + 6 * j + 4));
        wp2[j] = pack2(__ldg(wo + 6 * j + 2), __ldg(wo + 6 * j + 5));
    }
    float bias = (q == 0) ? __ldg(b2 + o) : 0.f;
    float* outbuf = g_f2p[q];

    int vbase = blockIdx.x * K4_STRIP;
    if (vbase >= V) return;
    int vend = vbase + K4_STRIP; if (vend > V) vend = V;

    float d0m, d0c, d1c, tA, tB;
    k4q_dots(vbase - 1, V, q, wp0, wp1, wp2, d0m, tA, tB);
    k4q_dots(vbase,     V, q, wp0, wp1, wp2, d0c, d1c, tB);

    #pragma unroll 4
    for (int v = vbase; v < vend; v++) {
        float e0, e1, e2;
        k4q_dots(v + 1, V, q, wp0, wp1, wp2, e0, e1, e2);
        outbuf[(size_t)v * 64 + o] = d0m + d1c + e2 + bias;
        d0m = d0c; d0c = e0; d1c = e1;
    }
}

// ============================================================
// K5 (K-split, reg-budgeted): logits = f2 @ wfc.T + bfc ; softmax
//   512 threads: thread = (output-pair p = tid&255, K-half kh = tid>>8).
//   REGISTER BUDGET (hard cap 128 @ 512 thr): wpair 32 ull = 64 regs,
//   acc[4] = 8, l0/l1[4] = 16 (reused for exp) + misc ~20  =>  ~108, NO SPILLS
//   (R13's 8-vertex tile overflowed the cap -> spill cliff -> timeout).
//   4-vertex tile; kh partials combined via smem; softmax on kh=0 warps.
// ============================================================
#define K5_TILE 4
__global__ __launch_bounds__(512) void k5_fc(const float* __restrict__ wfc,
                                             const float* __restrict__ bfc,
                                             float* __restrict__ out, int V) {
    __shared__ __align__(16) unsigned long long f2s[K5_TILE * 64];    // duplicated f2
    __shared__ __align__(16) unsigned long long part[K5_TILE * 256];  // kh=1 partials
    __shared__ float smax[K5_TILE * 8];
    __shared__ float ssum[K5_TILE * 8];
    int tid  = threadIdx.x;
    int lane = tid & 31, warp = tid >> 5;        // warp 0..15
    int p    = tid & 255;                        // output pair (2p, 2p+1)
    int kh   = tid >> 8;                         // K-half 0/1

    unsigned long long wpair[32];
    const float* wa = wfc + (2 * p) * 64 + kh * 32;
    const float* wb = wfc + (2 * p + 1) * 64 + kh * 32;
    #pragma unroll
    for (int j = 0; j < 32; j++) wpair[j] = pack2(__ldg(wa + j), __ldg(wb + j));
    unsigned long long bp = (kh == 0)
        ? pack2(__ldg(bfc + 2 * p), __ldg(bfc + 2 * p + 1)) : 0ull;

    for (int vbase = blockIdx.x * K5_TILE; vbase < V; vbase += gridDim.x * K5_TILE) {
        // staging: 256 values, threads 0..255
        if (tid < 256) {
            int lv = tid >> 6, lc = tid & 63;
            int vl = vbase + lv;
            float fv = 0.f;
            if (vl < V) {
                size_t ix = (size_t)vl * 64 + lc;
                fv = g_f2p[0][ix] + g_f2p[1][ix] + g_f2p[2][ix] + g_f2p[3][ix];
            }
            f2s[tid] = pack2(fv, fv);
        }
        __syncthreads();

        unsigned long long acc[K5_TILE];
        #pragma unroll
        for (int t = 0; t < K5_TILE; t++) acc[t] = bp;
        const ulonglong2* f2s2 = (const ulonglong2*)f2s;   // [t][32] ull pairs
        #pragma unroll
        for (int c2 = 0; c2 < 16; c2++) {                  // my K-half: 16 ull2
            int ci = kh * 16 + c2;
            #pragma unroll
            for (int t = 0; t < K5_TILE; t++) {
                ulonglong2 qv = f2s2[t * 32 + ci];
                acc[t] = fma2(wpair[2 * c2], qv.x, acc[t]);
                acc[t] = fma2(wpair[2 * c2 + 1], qv.y, acc[t]);
            }
        }
        // combine K-halves
        if (kh == 1) {
            #pragma unroll
            for (int t = 0; t < K5_TILE; t++) part[t * 256 + p] = acc[t];
        }
        __syncthreads();

        float l0[K5_TILE], l1[K5_TILE];
        if (kh == 0) {
            #pragma unroll
            for (int t = 0; t < K5_TILE; t++) {
                acc[t] = add2(acc[t], part[t * 256 + p]);
                unpack2(acc[t], l0[t], l1[t]);
            }
            // phase A: per-warp max (warps 0..7)
            #pragma unroll
            for (int t = 0; t < K5_TILE; t++) {
                float m = fmaxf(l0[t], l1[t]);
                #pragma unroll
                for (int s = 16; s > 0; s >>= 1)
                    m = fmaxf(m, __shfl_xor_sync(0xffffffffu, m, s));
                if (lane == 0) smax[t * 8 + warp] = m;
            }
        }
        __syncthreads();

        if (kh == 0) {
            #pragma unroll
            for (int t = 0; t < K5_TILE; t++) {
                float bm = smax[t * 8];
                #pragma unroll
                for (int j = 1; j < 8; j++) bm = fmaxf(bm, smax[t * 8 + j]);
                l0[t] = __expf(l0[t] - bm);              // reuse l as exp
                l1[t] = __expf(l1[t] - bm);
                float s = l0[t] + l1[t];
                #pragma unroll
                for (int sh2 = 16; sh2 > 0; sh2 >>= 1)
                    s += __shfl_xor_sync(0xffffffffu, s, sh2);
                if (lane == 0) ssum[t * 8 + warp] = s;
            }
        }
        __syncthreads();

        if (kh == 0) {
            #pragma unroll
            for (int t = 0; t < K5_TILE; t++) {
                int v = vbase + t;
                if (v < V) {
                    float bs = ssum[t * 8];
                    #pragma unroll
                    for (int j = 1; j < 8; j++) bs += ssum[t * 8 + j];
                    float inv = 1.0f / bs;
                    ((float2*)out)[(size_t)v * 256 + p] =
                        make_float2(l0[t] * inv, l1[t] * inv);
                }
            }
        }
        __syncthreads();
    }
}

// ============================================================
// Launch: bind inputs BY ELEMENT COUNT (robust to metadata ordering).
// ============================================================
extern "C" void kernel_launch(void* const* d_in, const int* in_sizes, int n_in,
                              void* d_out, int out_size) {
    long long mx = 0;
    for (int i = 0; i < n_in; i++) if ((long long)in_sizes[i] > mx) mx = in_sizes[i];
    int V = (int)(mx / 32);
    if (V > V_MAX) V = V_MAX;

    const float *vp = 0, *wv1 = 0, *bv1 = 0, *w1 = 0, *b1 = 0;
    const float *wv2 = 0, *bv2 = 0, *w2 = 0, *b2 = 0, *wfc = 0, *bfc = 0;
    const int *nb1 = 0, *nb2 = 0;

    int nb_seen = 0, wv_seen = 0, bv_seen = 0;
    for (int i = 0; i < n_in; i++) {
        long long s = in_sizes[i];
        const void* p = d_in[i];
        if (s == mx)            { if (nb_seen++ == 0) nb1 = (const int*)p; else nb2 = (const int*)p; }
        else if (s == V)        { vp  = (const float*)p; }
        else if (s == 3)        { if (wv_seen++ == 0) wv1 = (const float*)p; else wv2 = (const float*)p; }
        else if (s == 1)        { if (bv_seen++ == 0) bv1 = (const float*)p; else bv2 = (const float*)p; }
        else if (s == 96)       { w1  = (const float*)p; }
        else if (s == 32)       { b1  = (const float*)p; }
        else if (s == 6144)     { w2  = (const float*)p; }
        else if (s == 64)       { b2  = (const float*)p; }
        else if (s == 32768)    { wfc = (const float*)p; }
        else if (s == 512)      { bfc = (const float*)p; }
    }
    if (!vp || !nb1 || !nb2 || !wv1 || !bv1 || !w1 || !b1 ||
        !wv2 || !bv2 || !w2 || !b2 || !wfc || !bfc) return;
    float* out = (float*)d_out;

    int k12Blocks = (V + K12_VPB - 1) / K12_VPB;
    int warpBlocks = (V + 7) / 8;                 // 8 warps (256 thr) per block
    int k4Blocks = (V + K4_STRIP - 1) / K4_STRIP;
    k12  <<<k12Blocks, 320>>>(vp, nb1, wv1, bv1, w1, b1, V);
    k3_h2<<<warpBlocks, 256>>>(nb2, wv2, bv2, V);
    k4_f2<<<k4Blocks, 256>>>(w2, b2, V);
    k5_fc<<<148, 512>>>(wfc, bfc, out, V);
}

// round 17
// speedup vs baseline: 1.3752x; 1.3752x over previous
#include <cuda_runtime.h>

#define V_MAX 100000

// -------- scratch (static device arrays; no allocation) --------
__device__ float g_f1[V_MAX * 32];
__device__ float g_h2[V_MAX * 32];
__device__ float g_f2p[4][V_MAX * 64];   // k4 partial sums (channel quarters)

// -------- f32x2 packed helpers --------
__device__ __forceinline__ unsigned long long pack2(float lo, float hi) {
    unsigned long long r;
    asm("mov.b64 %0, {%1, %2};" : "=l"(r) : "f"(lo), "f"(hi));
    return r;
}
__device__ __forceinline__ void unpack2(unsigned long long v, float& lo, float& hi) {
    asm("mov.b64 {%0, %1}, %2;" : "=f"(lo), "=f"(hi) : "l"(v));
}
__device__ __forceinline__ unsigned long long fma2(unsigned long long a,
                                                   unsigned long long b,
                                                   unsigned long long c) {
    unsigned long long d;
    asm("fma.rn.f32x2 %0, %1, %2, %3;" : "=l"(d) : "l"(a), "l"(b), "l"(c));
    return d;
}

// ============================================================
// K12 (fused K1+K2): block covers 8 vertices + 2 halo.
// ============================================================
#define K12_VPB 8
__global__ __launch_bounds__(320) void k12(const float* __restrict__ vp,
                                           const int* __restrict__ nb1,
                                           const float* __restrict__ wv1,
                                           const float* __restrict__ bv1,
                                           const float* __restrict__ w1,
                                           const float* __restrict__ b1, int V) {
    __shared__ float sh[K12_VPB + 2];
    int tid = threadIdx.x, w = tid >> 5, lane = tid & 31;
    int vbase = blockIdx.x * K12_VPB;
    int vg = vbase - 1 + w;                      // w in 0..9

    float hval = 0.f;
    if ((unsigned)vg < (unsigned)V) {
        int j = nb1[(size_t)vg * 32 + lane];
        if ((unsigned)j >= (unsigned)V) j = 0;   // defensive clamp
        float g = vp[j];
        float c0 = __ldg(wv1 + 0), c1 = __ldg(wv1 + 1), c2 = __ldg(wv1 + 2);
        float b  = __ldg(bv1);
        float gm = __shfl_up_sync(0xffffffffu, g, 1);
        if (lane == 0) gm = 0.f;
        float gp = __shfl_down_sync(0xffffffffu, g, 1);
        if (lane == 31) gp = 0.f;
        float a = fmaxf(c0 * gm + c1 * g + c2 * gp + b, 0.f);
        #pragma unroll
        for (int s = 16; s > 0; s >>= 1) a += __shfl_xor_sync(0xffffffffu, a, s);
        hval = a * (1.0f / 32.0f);
    }
    if (lane == 0) sh[w] = hval;                 // out-of-range vg -> 0 (pad)
    __syncthreads();

    if (tid < 256) {
        int lv = tid >> 5;
        int v = vbase + lv;
        if (v < V) {
            float hm = sh[lv], hc = sh[lv + 1], hp = sh[lv + 2];
            int c = lane;
            g_f1[(size_t)v * 32 + c] =
                hm * __ldg(w1 + c * 3 + 0) + hc * __ldg(w1 + c * 3 + 1)
              + hp * __ldg(w1 + c * 3 + 2) + __ldg(b1 + c);
        }
    }
}

// ============================================================
// K3: h2[v,c] = mean_n relu(conv_k3_over_n( f1[nb2[v,n], c] ))
//     warp per vertex, lane = channel c; 32 row loads upfront (MLP=32).
// ============================================================
__global__ void k3_h2(const int* __restrict__ nb2, const float* __restrict__ wv2,
                      const float* __restrict__ bv2, int V) {
    int warp = (blockIdx.x * blockDim.x + threadIdx.x) >> 5;
    int lane = threadIdx.x & 31;
    if (warp >= V) return;
    int idx = nb2[(size_t)warp * 32 + lane];
    if ((unsigned)idx >= (unsigned)V) idx = 0;  // defensive clamp

    float gv[32];
    #pragma unroll
    for (int p = 0; p < 32; p++) {
        int rn = __shfl_sync(0xffffffffu, idx, p);
        gv[p] = __ldg(&g_f1[(size_t)rn * 32 + lane]);  // coalesced 128B row
    }
    float w0 = __ldg(wv2 + 0), w1 = __ldg(wv2 + 1), w2 = __ldg(wv2 + 2);
    float b  = __ldg(bv2);
    float acc = 0.f;
    #pragma unroll
    for (int p = 0; p < 32; p++) {
        float gm = (p > 0)  ? gv[p - 1] : 0.f;
        float gp = (p < 31) ? gv[p + 1] : 0.f;
        acc += fmaxf(w0 * gm + w1 * gv[p] + w2 * gp + b, 0.f);
    }
    g_h2[(size_t)warp * 32 + lane] = acc * (1.0f / 32.0f);
}

// ============================================================
// K4: 4-way channel split, rolling tap-dots, ull2 row loads.
// ============================================================
#define K4_STRIP 64

__device__ __forceinline__ void k4q_dots(
    int r, int V, int q,
    const unsigned long long* wp0, const unsigned long long* wp1,
    const unsigned long long* wp2,
    float& e0, float& e1, float& e2)
{
    if ((unsigned)r >= (unsigned)V) { e0 = 0.f; e1 = 0.f; e2 = 0.f; return; }
    const ulonglong2* row = (const ulonglong2*)(g_h2 + (size_t)r * 32 + q * 8);
    ulonglong2 ua = __ldg(row);
    ulonglong2 ub = __ldg(row + 1);
    unsigned long long a0 = fma2(ua.x, wp0[0], 0ull);
    unsigned long long a1 = fma2(ua.x, wp1[0], 0ull);
    unsigned long long a2 = fma2(ua.x, wp2[0], 0ull);
    a0 = fma2(ua.y, wp0[1], a0);  a1 = fma2(ua.y, wp1[1], a1);  a2 = fma2(ua.y, wp2[1], a2);
    a0 = fma2(ub.x, wp0[2], a0);  a1 = fma2(ub.x, wp1[2], a1);  a2 = fma2(ub.x, wp2[2], a2);
    a0 = fma2(ub.y, wp0[3], a0);  a1 = fma2(ub.y, wp1[3], a1);  a2 = fma2(ub.y, wp2[3], a2);
    float lo, hi;
    unpack2(a0, lo, hi); e0 = lo + hi;
    unpack2(a1, lo, hi); e1 = lo + hi;
    unpack2(a2, lo, hi); e2 = lo + hi;
}

__global__ __launch_bounds__(256, 4) void k4_f2(const float* __restrict__ w2,
                                                const float* __restrict__ b2, int V) {
    int tid = threadIdx.x;
    int o = tid & 63;
    int q = tid >> 6;                            // channel quarter 0..3

    const float* wo = w2 + o * 96 + q * 24;
    unsigned long long wp0[4], wp1[4], wp2[4];
    #pragma unroll
    for (int j = 0; j < 4; j++) {
        wp0[j] = pack2(__ldg(wo + 6 * j + 0), __ldg(wo + 6 * j + 3));
        wp1[j] = pack2(__ldg(wo + 6 * j + 1), __ldg(wo + 6 * j + 4));
        wp2[j] = pack2(__ldg(wo + 6 * j + 2), __ldg(wo + 6 * j + 5));
    }
    float bias = (q == 0) ? __ldg(b2 + o) : 0.f;
    float* outbuf = g_f2p[q];

    int vbase = blockIdx.x * K4_STRIP;
    if (vbase >= V) return;
    int vend = vbase + K4_STRIP; if (vend > V) vend = V;

    float d0m, d0c, d1c, tA, tB;
    k4q_dots(vbase - 1, V, q, wp0, wp1, wp2, d0m, tA, tB);
    k4q_dots(vbase,     V, q, wp0, wp1, wp2, d0c, d1c, tB);

    #pragma unroll 4
    for (int v = vbase; v < vend; v++) {
        float e0, e1, e2;
        k4q_dots(v + 1, V, q, wp0, wp1, wp2, e0, e1, e2);
        outbuf[(size_t)v * 64 + o] = d0m + d1c + e2 + bias;
        d0m = d0c; d0c = e0; d1c = e1;
    }
}

// ============================================================
// K5a (pure GEMM): logits[v,o] = f2[v,:] . wfc[o,:] + bfc[o]
//   Persistent 148 blocks x 512 threads; thread owns output o.
//   Weights: 32 packed ull (channel pairs) = 64 regs. No duplication,
//   no combine, no softmax -> ONE barrier per 8-vertex tile, double-
//   buffered f2 staging. 4 independent acc chains per vertex (ILP).
//   Logits stream to d_out (in-place softmax by k5b afterwards).
// ============================================================
#define K5A_TILE 8
__global__ __launch_bounds__(512) void k5a(const float* __restrict__ wfc,
                                           const float* __restrict__ bfc,
                                           float* __restrict__ logits, int V) {
    __shared__ __align__(16) float f2s[2][K5A_TILE * 64];
    int tid = threadIdx.x;                       // == output o
    int o = tid;

    unsigned long long wpair[32];                // (wfc[o][2j], wfc[o][2j+1])
    const float2* wrow = (const float2*)(wfc + (size_t)o * 64);
    #pragma unroll
    for (int j = 0; j < 32; j++) {
        float2 wv = __ldg(wrow + j);
        wpair[j] = pack2(wv.x, wv.y);
    }
    float bias = __ldg(bfc + o);

    int nTiles = (V + K5A_TILE - 1) / K5A_TILE;

    // stage first tile into buf 0
    {
        int tId = blockIdx.x;
        if (tId < nTiles) {
            int lv = tid >> 6, lc = tid & 63;
            int vl = tId * K5A_TILE + lv;
            float fv = 0.f;
            if (vl < V) {
                size_t ix = (size_t)vl * 64 + lc;
                fv = g_f2p[0][ix] + g_f2p[1][ix] + g_f2p[2][ix] + g_f2p[3][ix];
            }
            f2s[0][lv * 64 + lc] = fv;
        }
    }
    __syncthreads();

    int buf = 0;
    for (int tId = blockIdx.x; tId < nTiles; tId += gridDim.x) {
        // stage next tile into buf^1 (overlaps with compute below)
        int nId = tId + gridDim.x;
        if (nId < nTiles) {
            int lv = tid >> 6, lc = tid & 63;
            int vl = nId * K5A_TILE + lv;
            float fv = 0.f;
            if (vl < V) {
                size_t ix = (size_t)vl * 64 + lc;
                fv = g_f2p[0][ix] + g_f2p[1][ix] + g_f2p[2][ix] + g_f2p[3][ix];
            }
            f2s[buf ^ 1][lv * 64 + lc] = fv;
        }

        int vbase = tId * K5A_TILE;
        int nv = V - vbase; if (nv > K5A_TILE) nv = K5A_TILE;
        for (int lv = 0; lv < nv; lv++) {
            const ulonglong2* row = (const ulonglong2*)&f2s[buf][lv * 64];
            unsigned long long a0 = 0ull, a1 = 0ull, a2 = 0ull, a3 = 0ull;
            #pragma unroll
            for (int j = 0; j < 16; j += 4) {    // 16 LDS.128, 32 FFMA2
                ulonglong2 p0 = row[j + 0];
                ulonglong2 p1 = row[j + 1];
                ulonglong2 p2 = row[j + 2];
                ulonglong2 p3 = row[j + 3];
                a0 = fma2(wpair[2 * j + 0], p0.x, a0);
                a0 = fma2(wpair[2 * j + 1], p0.y, a0);
                a1 = fma2(wpair[2 * j + 2], p1.x, a1);
                a1 = fma2(wpair[2 * j + 3], p1.y, a1);
                a2 = fma2(wpair[2 * j + 4], p2.x, a2);
                a2 = fma2(wpair[2 * j + 5], p2.y, a2);
                a3 = fma2(wpair[2 * j + 6], p3.x, a3);
                a3 = fma2(wpair[2 * j + 7], p3.y, a3);
            }
            float s0, s1, t0, t1;
            unpack2(a0, s0, t0); unpack2(a1, s1, t1);
            float r0 = (s0 + t0) + (s1 + t1);
            unpack2(a2, s0, t0); unpack2(a3, s1, t1);
            float r1 = (s0 + t0) + (s1 + t1);
            logits[(size_t)(vbase + lv) * 512 + o] = r0 + r1 + bias;
        }
        __syncthreads();   // next stage complete + buf free for re-stage
        buf ^= 1;
    }
}

// ============================================================
// K5b: in-place softmax on logits rows of 512 (warp per vertex).
//   No block barriers; fully parallel; memory-bound.
// ============================================================
__global__ __launch_bounds__(256) void k5b(float* __restrict__ buf, int V) {
    int warp = (blockIdx.x * blockDim.x + threadIdx.x) >> 5;
    int lane = threadIdx.x & 31;
    if (warp >= V) return;
    float4* row = (float4*)(buf + (size_t)warp * 512);   // 128 float4

    float4 x[4];
    #pragma unroll
    for (int r = 0; r < 4; r++) x[r] = row[lane + r * 32];

    float m = -1e30f;
    #pragma unroll
    for (int r = 0; r < 4; r++) {
        m = fmaxf(m, fmaxf(fmaxf(x[r].x, x[r].y), fmaxf(x[r].z, x[r].w)));
    }
    #pragma unroll
    for (int s = 16; s > 0; s >>= 1) m = fmaxf(m, __shfl_xor_sync(0xffffffffu, m, s));

    float sum = 0.f;
    #pragma unroll
    for (int r = 0; r < 4; r++) {
        x[r].x = __expf(x[r].x - m); x[r].y = __expf(x[r].y - m);
        x[r].z = __expf(x[r].z - m); x[r].w = __expf(x[r].w - m);
        sum += (x[r].x + x[r].y) + (x[r].z + x[r].w);
    }
    #pragma unroll
    for (int s = 16; s > 0; s >>= 1) sum += __shfl_xor_sync(0xffffffffu, sum, s);
    float inv = 1.0f / sum;

    #pragma unroll
    for (int r = 0; r < 4; r++) {
        x[r].x *= inv; x[r].y *= inv; x[r].z *= inv; x[r].w *= inv;
        row[lane + r * 32] = x[r];
    }
}

// ============================================================
// Launch: bind inputs BY ELEMENT COUNT (robust to metadata ordering).
// ============================================================
extern "C" void kernel_launch(void* const* d_in, const int* in_sizes, int n_in,
                              void* d_out, int out_size) {
    long long mx = 0;
    for (int i = 0; i < n_in; i++) if ((long long)in_sizes[i] > mx) mx = in_sizes[i];
    int V = (int)(mx / 32);
    if (V > V_MAX) V = V_MAX;

    const float *vp = 0, *wv1 = 0, *bv1 = 0, *w1 = 0, *b1 = 0;
    const float *wv2 = 0, *bv2 = 0, *w2 = 0, *b2 = 0, *wfc = 0, *bfc = 0;
    const int *nb1 = 0, *nb2 = 0;

    int nb_seen = 0, wv_seen = 0, bv_seen = 0;
    for (int i = 0; i < n_in; i++) {
        long long s = in_sizes[i];
        const void* p = d_in[i];
        if (s == mx)            { if (nb_seen++ == 0) nb1 = (const int*)p; else nb2 = (const int*)p; }
        else if (s == V)        { vp  = (const float*)p; }
        else if (s == 3)        { if (wv_seen++ == 0) wv1 = (const float*)p; else wv2 = (const float*)p; }
        else if (s == 1)        { if (bv_seen++ == 0) bv1 = (const float*)p; else bv2 = (const float*)p; }
        else if (s == 96)       { w1  = (const float*)p; }
        else if (s == 32)       { b1  = (const float*)p; }
        else if (s == 6144)     { w2  = (const float*)p; }
        else if (s == 64)       { b2  = (const float*)p; }
        else if (s == 32768)    { wfc = (const float*)p; }
        else if (s == 512)      { bfc = (const float*)p; }
    }
    if (!vp || !nb1 || !nb2 || !wv1 || !bv1 || !w1 || !b1 ||
        !wv2 || !bv2 || !w2 || !b2 || !wfc || !bfc) return;
    float* out = (float*)d_out;

    int k12Blocks = (V + K12_VPB - 1) / K12_VPB;
    int warpBlocks = (V + 7) / 8;                 // 8 warps (256 thr) per block
    int k4Blocks = (V + K4_STRIP - 1) / K4_STRIP;
    k12  <<<k12Blocks, 320>>>(vp, nb1, wv1, bv1, w1, b1, V);
    k3_h2<<<warpBlocks, 256>>>(nb2, wv2, bv2, V);
    k4_f2<<<k4Blocks, 256>>>(w2, b2, V);
    k5a  <<<148, 512>>>(wfc, bfc, out, V);
    k5b  <<<warpBlocks, 256>>>(out, V);
}